// round 15
// baseline (speedup 1.0000x reference)
#include <cuda_runtime.h>
#include <math.h>

#define NANC   10647
#define KSTR   10648                   // padded per-image key stride (even -> 16B-aligned pairs)
#define NBOX   50
#define BATCH  32
#define NCLS   20
#define NUMNEG 1000

#define DEC_NB 21                      // decode blocks per image (256 thr, 2 anchors/thr)
#define POS_NB 2                       // positive-loss blocks per image (25 boxes each)
#define SEL_X  (DEC_NB + POS_NB)       // x index of the select block
#define GRID_X (SEL_X + 1)             // 24
#define FIN_TOTAL (BATCH * (POS_NB + 1))   // pos + select blocks that gate the final sum

// ---------------- scratch (static device globals: no runtime allocation) ----------------
__device__ __align__(16) unsigned long long g_keys[BATCH * KSTR];
__device__ float               g_neg [BATCH];
__device__ __align__(16) float g_pos [BATCH * NBOX];
__device__ int                 g_done[BATCH];         // decode blocks finished per image
__device__ unsigned            g_ctr;                 // final-gate counter (wraps)

// ---------------- constants ----------------
__constant__ float c_asc_x[9] = {10.f/416.f,16.f/416.f,33.f/416.f,30.f/416.f,62.f/416.f,
                                 59.f/416.f,116.f/416.f,156.f/416.f,373.f/416.f};
__constant__ float c_asc_y[9] = {13.f/416.f,30.f/416.f,23.f/416.f,61.f/416.f,45.f/416.f,
                                 119.f/416.f,90.f/416.f,198.f/416.f,326.f/416.f};
__constant__ float c_fs9[9]   = {52.f,52.f,52.f,26.f,26.f,26.f,13.f,13.f,13.f};
__constant__ int   c_cum[3]   = {0, 2704, 3380};
__constant__ int   c_fsl[3]   = {52, 26, 13};

// ---------------- math helpers ----------------
// R5-exact CIoU (pos path; discrete argmax selections stay bit-stable vs R5)
__device__ __forceinline__ float ciou_f(float l1,float t1,float r1,float b1,
                                        float areaE1,float at1,float cx1,float cy1,
                                        float l2,float t2,float r2,float b2,
                                        float area2,float at2,float cx2,float cy2)
{
    float iw = fminf(r1,r2) - fmaxf(l1,l2); iw = fmaxf(iw, 0.f);
    float ih = fminf(b1,b2) - fmaxf(t1,t2); ih = fmaxf(ih, 0.f);
    float inter = iw * ih;
    float uni   = (areaE1 + area2) - inter;
    float iou   = __fdividef(inter, uni);
    float cw = fmaxf(r1,r2) - fminf(l1,l2);
    float ch = fmaxf(b1,b2) - fminf(t1,t2);
    float c2 = fmaf(cw, cw, fmaf(ch, ch, 1e-7f));
    float dx = cx1 - cx2, dy = cy1 - cy2;
    float rho2 = fmaf(dx, dx, dy * dy);
    float dd = at1 - at2;
    float v  = 0.40528473456935109f * dd * dd;
    float den = (1.0000001f - iou) + v;
    float av  = v * __fdividef(v, den);
    return iou - __fdividef(rho2, c2) - av;
}

// 2-divide variant for the 17M-pair OHEM loop (rho2/c2 + v^2/den combined)
__device__ __forceinline__ float ciou_f2(float l1,float t1,float r1,float b1,
                                         float areaE1,float at1,float cx1,float cy1,
                                         float l2,float t2,float r2,float b2,
                                         float area2,float at2,float cx2,float cy2)
{
    float iw = fminf(r1,r2) - fmaxf(l1,l2); iw = fmaxf(iw, 0.f);
    float ih = fminf(b1,b2) - fmaxf(t1,t2); ih = fmaxf(ih, 0.f);
    float inter = iw * ih;
    float uni   = (areaE1 + area2) - inter;
    float iou   = __fdividef(inter, uni);
    float cw = fmaxf(r1,r2) - fminf(l1,l2);
    float ch = fmaxf(b1,b2) - fminf(t1,t2);
    float c2 = fmaf(cw, cw, fmaf(ch, ch, 1e-7f));
    float dx = cx1 - cx2, dy = cy1 - cy2;
    float rho2 = fmaf(dx, dx, dy * dy);
    float dd = at1 - at2;
    float v  = 0.40528473456935109f * dd * dd;
    float den = (1.0000001f - iou) + v;
    float num = fmaf(rho2, den, (v * v) * c2);     // rho2*den + v^2*c2
    return iou - __fdividef(num, c2 * den);
}

__device__ __forceinline__ float softplusf(float x){
    return fmaxf(x, 0.f) + log1pf(expf(-fabsf(x)));
}
__device__ __forceinline__ float sigmf(float x){ return 1.f / (1.f + expf(-x)); }
__device__ __forceinline__ float focal0(float x){
    float s = sigmf(x); return softplusf(x) * 0.75f * s * s;
}
__device__ __forceinline__ float focal1(float x){
    float s = sigmf(x); float o = 1.f - s;
    return (softplusf(x) - x) * 0.25f * o * o;
}
__device__ __forceinline__ unsigned ordf(float f){
    unsigned u = __float_as_uint(f);
    return (u & 0x80000000u) ? ~u : (u | 0x80000000u);
}
__device__ __forceinline__ float fs_of(int a){
    return (a < 8112) ? 52.f : ((a < 10140) ? 26.f : 13.f);
}

struct AncReg { float l, t, r, b, area, at, cx, cy; };

__device__ __forceinline__ AncReg decode_anchor(const float* __restrict__ p,
                                                const float* __restrict__ ancs,
                                                int b, int a)
{
    const float* pp = p + ((size_t)b * NANC + a) * 25;
    float4 an = ((const float4*)ancs)[a];
    float fs = fs_of(a);
    float cx = (1.f / (1.f + expf(-pp[0]))) / fs + an.x;
    float cy = (1.f / (1.f + expf(-pp[1]))) / fs + an.y;
    float w  = expf(pp[2]) * an.z;
    float h  = expf(pp[3]) * an.w;
    AncReg R;
    R.l = cx - w * 0.5f; R.t = cy - h * 0.5f;
    R.r = cx + w * 0.5f; R.b = cy + h * 0.5f;
    R.area = w * h;
    R.at   = atanf(w / (h + 1e-7f));
    R.cx   = cx;  R.cy = cy;
    return R;
}

// ================================ the single fused kernel ================================
__global__ void k_fused(const float* __restrict__ p, const float* __restrict__ boxes,
                        const int* __restrict__ labels, const float* __restrict__ ancs,
                        float* __restrict__ out)
{
    const int b    = blockIdx.y;
    const int bx   = blockIdx.x;
    const int t    = threadIdx.x;
    const int lane = t & 31;

    // ---------------------------------- DECODE path ----------------------------------
    if (bx < DEC_NB) {
        __shared__ float4 sA[NBOX];   // l,t,r,b
        __shared__ float4 sB[NBOX];   // area+eps, atan, cx, cy
        if (t < NBOX) {
            float4 bxv = ((const float4*)boxes)[b * NBOX + t];
            sA[t] = bxv;
            float w = bxv.z - bxv.x, h = bxv.w - bxv.y;
            sB[t] = make_float4(w * h + 1e-7f, atanf(w / (h + 1e-7f)),
                                (bxv.x + bxv.z) * 0.5f, (bxv.y + bxv.w) * 0.5f);
        }
        __syncthreads();

        int a0 = (bx * 256 + t) * 2;
        if (a0 < NANC) {
            const int  a1   = a0 + 1;
            const bool has1 = (a1 < NANC);
            AncReg X = decode_anchor(p, ancs, b, a0);
            AncReg Y = has1 ? decode_anchor(p, ancs, b, a1) : X;

            float mx0 = -1e30f, mx1 = -1e30f;
            #pragma unroll 2
            for (int i = 0; i < NBOX; i++) {
                float4 A  = sA[i];
                float4 Bb = sB[i];
                mx0 = fmaxf(mx0, ciou_f2(A.x, A.y, A.z, A.w, Bb.x, Bb.y, Bb.z, Bb.w,
                                         X.l, X.t, X.r, X.b, X.area, X.at, X.cx, X.cy));
                mx1 = fmaxf(mx1, ciou_f2(A.x, A.y, A.z, A.w, Bb.x, Bb.y, Bb.z, Bb.w,
                                         Y.l, Y.t, Y.r, Y.b, Y.area, Y.at, Y.cx, Y.cy));
            }
            float m0 = (mx0 < 0.5f) ? mx0 : __int_as_float(0x7f800000);
            unsigned long long k0 =
                (((unsigned long long)ordf(m0)) << 32) | (unsigned)a0;
            if (has1) {
                float m1 = (mx1 < 0.5f) ? mx1 : __int_as_float(0x7f800000);
                unsigned long long k1 =
                    (((unsigned long long)ordf(m1)) << 32) | (unsigned)a1;
                // KSTR even + a0 even -> 16-byte aligned: single STG.128
                *reinterpret_cast<ulonglong2*>(&g_keys[(size_t)b * KSTR + a0]) =
                    make_ulonglong2(k0, k1);
            } else {
                g_keys[(size_t)b * KSTR + a0] = k0;
            }
        }
        __syncthreads();                      // all block stores done
        __threadfence();                      // publish before counting
        if (t == 0) atomicAdd(&g_done[b], 1);
        return;
    }

    // ---------------------------------- POSITIVES path ----------------------------------
    if (bx < SEL_X) {
        __shared__ float s_l[NBOX], s_t[NBOX], s_r[NBOX], s_bb[NBOX], s_cx[NBOX], s_cy[NBOX];
        if (t < NBOX) {
            float4 bxv = ((const float4*)boxes)[b * NBOX + t];
            s_l[t] = bxv.x; s_t[t] = bxv.y; s_r[t] = bxv.z; s_bb[t] = bxv.w;
            s_cx[t] = (bxv.x + bxv.z) * 0.5f;
            s_cy[t] = (bxv.y + bxv.w) * 0.5f;
        }
        __syncthreads();

        const int sub = bx - DEC_NB;          // 0 or 1 -> boxes [sub*25, sub*25+25)
        const int w   = t >> 5;               // 8 warps, each takes boxes w, w+8, ...
        for (int i = sub * 25 + w; i < sub * 25 + 25; i += 8) {
            float l1 = s_l[i], t1 = s_t[i], r1 = s_r[i], b1 = s_bb[i];
            float w1 = r1 - l1, h1 = b1 - t1;
            float area1  = w1 * h1;
            float areaE1 = area1 + 1e-7f;
            float at1    = atanf(w1 / (h1 + 1e-7f));
            float off1   = (float)i;
            float l1o = l1 + off1, t1o = t1 + off1, r1o = r1 + off1, b1o = b1 + off1;
            float cx1o = (l1o + r1o) * 0.5f, cy1o = (t1o + b1o) * 0.5f;

            float best = -1e30f; int bestj = 1 << 30;
            for (int j = lane; j < NBOX * 9; j += 32) {
                int jb = j / 9, a9 = j - jb * 9;
                float f = c_fs9[a9];
                float acx = floorf(s_cx[jb] * f) / f;
                float acy = floorf(s_cy[jb] * f) / f;
                float aw = c_asc_x[a9], ah = c_asc_y[a9];
                float offj = (float)jb;
                float l2 = acx - aw * 0.5f + offj, t2 = acy - ah * 0.5f + offj;
                float r2 = acx + aw * 0.5f + offj, b2 = acy + ah * 0.5f + offj;
                float w2 = r2 - l2, h2 = b2 - t2;
                float v = ciou_f(l1o, t1o, r1o, b1o, areaE1, at1, cx1o, cy1o,
                                 l2, t2, r2, b2, w2 * h2, atanf(w2 / (h2 + 1e-7f)),
                                 (l2 + r2) * 0.5f, (t2 + b2) * 0.5f);
                if (v > best) { best = v; bestj = j; }   // ascending j -> first-max per lane
            }
            #pragma unroll
            for (int o = 16; o > 0; o >>= 1) {           // argmax, tie -> smaller j
                float ov = __shfl_xor_sync(0xffffffffu, best, o);
                int   oj = __shfl_xor_sync(0xffffffffu, bestj, o);
                if (ov > best || (ov == best && oj < bestj)) { best = ov; bestj = oj; }
            }
            int kk  = bestj % 9;
            int lev = kk / 3;
            float ff = c_fs9[kk];
            int col = (int)floorf(s_cx[i] * ff);
            int row = (int)floorf(s_cy[i] * ff);
            int midx = (c_cum[lev] + row * c_fsl[lev] + col) * 3 + lev;

            const float* pm = p + ((size_t)b * NANC + midx) * 25;
            int lab = labels[b * NBOX + i] - 1;
            float contrib = 0.f;
            if (lane < NCLS) {                            // l_cls, one class per lane
                float x = pm[5 + lane];
                contrib = softplusf(x) - ((lane == lab) ? x : 0.f);
            } else if (lane == NCLS) {                    // l_conf_pos
                contrib = focal1(pm[4]);
            } else if (lane == NCLS + 1) {                // l_iou
                float4 an = ((const float4*)ancs)[midx];
                float fsm = fs_of(midx);
                float pcx = (1.f / (1.f + expf(-pm[0]))) / fsm + an.x;
                float pcy = (1.f / (1.f + expf(-pm[1]))) / fsm + an.y;
                float pw  = expf(pm[2]) * an.z;
                float ph  = expf(pm[3]) * an.w;
                float pl = pcx - pw * 0.5f, pt = pcy - ph * 0.5f;
                float pr = pcx + pw * 0.5f, pb = pcy + ph * 0.5f;
                float iou1 = ciou_f(l1, t1, r1, b1, areaE1, at1,
                                    (l1 + r1) * 0.5f, (t1 + b1) * 0.5f,
                                    pl, pt, pr, pb, pw * ph,
                                    atanf(pw / (ph + 1e-7f)), pcx, pcy);
                contrib = (2.f - area1) * (1.f - iou1);
            }
            #pragma unroll
            for (int o = 16; o > 0; o >>= 1)
                contrib += __shfl_xor_sync(0xffffffffu, contrib, o);
            if (lane == 0) g_pos[b * NBOX + i] = contrib;
        }
    }
    // ---------------------------------- SELECT path ----------------------------------
    else {
        __shared__ unsigned hist[256];
        __shared__ unsigned long long s_pref;
        __shared__ int s_k, s_cnt, s_fin;
        __shared__ float s_red[8];

        if (t == 0) { s_fin = 0; s_cnt = 0; }
        // wait until this image's keys are published
        if (t == 0) {
            while (atomicAdd(&g_done[b], 0) < DEC_NB) __nanosleep(64);
        }
        __syncthreads();

        const unsigned long long* kb = g_keys + (size_t)b * KSTR;
        unsigned long long prefix = 0ull, pmask = 0ull;
        int k = NUMNEG;
        const int shifts[6] = {56, 48, 40, 32, 8, 0};

        for (int pi = 0; pi < 6; pi++) {
            if (pi == 4 && s_fin) break;                 // value threshold already exact
            const int shift = shifts[pi];
            hist[t] = 0u;
            __syncthreads();

            // UNIFORM trip count: every thread runs ceil(NANC/256) iterations so the
            // full-mask ballot below is legal; interior is guarded by i < NANC.
            for (int base = 0; base < NANC; base += 256) {
                int i = base + t;
                bool ok = false; unsigned digit = 0;
                if (i < NANC) {
                    unsigned long long e = __ldg(&kb[i]);
                    ok = ((e & pmask) == prefix);
                    digit = (unsigned)(e >> shift) & 255u;
                }
                unsigned bal = __ballot_sync(0xffffffffu, ok);
                if (ok) {
                    unsigned same = __match_any_sync(bal, digit);
                    if (lane == (__ffs(same) - 1))
                        atomicAdd(&hist[digit], __popc(same));
                }
            }
            __syncthreads();

            if (t < 32) {                                // warp-scan over 256 bins
                int lo = t * 8;
                unsigned c[8]; int lsum = 0;
                #pragma unroll
                for (int j = 0; j < 8; j++) { c[j] = hist[lo + j]; lsum += (int)c[j]; }
                int pre = lsum;
                #pragma unroll
                for (int o = 1; o < 32; o <<= 1) {
                    int n = __shfl_up_sync(0xffffffffu, pre, o);
                    if (t >= o) pre += n;
                }
                int excl = pre - lsum;
                if (excl < k && k <= excl + lsum) {
                    int run = excl, d = lo, cc = 0;
                    #pragma unroll
                    for (int j = 0; j < 8; j++) {
                        if (run + (int)c[j] >= k) { d = lo + j; cc = (int)c[j]; break; }
                        run += (int)c[j];
                    }
                    s_pref = prefix | ((unsigned long long)(unsigned)d << shift);
                    s_k    = k - run;
                    s_cnt  = cc;
                }
            }
            __syncthreads();
            prefix = s_pref; k = s_k;
            pmask |= (0xFFull << shift);
            if (pi == 3) {
                pmask |= (0xFFFFull << 16);              // key bytes 3,2 are always zero
                if (t == 0) s_fin = (s_k == s_cnt);      // all ties included -> done
            }
            __syncthreads();
        }
        unsigned long long thresh = s_fin ? (prefix | 0xFFFFFFFFull) : prefix;

        float sum = 0.f;                                 // exactly NUMNEG keys pass
        for (int i = t; i < NANC; i += 256) {
            unsigned long long e = __ldg(&kb[i]);
            if (e <= thresh) {
                int idx = (int)(unsigned)(e & 0xffffffffu);
                sum += focal0(p[((size_t)b * NANC + idx) * 25 + 4]);
            }
        }
        #pragma unroll
        for (int o = 16; o > 0; o >>= 1) sum += __shfl_xor_sync(0xffffffffu, sum, o);
        if (lane == 0) s_red[t >> 5] = sum;
        __syncthreads();
        if (t == 0) {
            float v = 0.f;
            #pragma unroll
            for (int j = 0; j < 8; j++) v += s_red[j];
            g_neg[b] = v;
        }
    }

    // ------------------------- common finalize gate (pos + select) -------------------------
    __shared__ int s_last;
    __shared__ double sdd[8];
    __syncthreads();
    __threadfence();
    if (t == 0) {
        unsigned old = atomicInc(&g_ctr, FIN_TOTAL - 1);
        s_last = (old == FIN_TOTAL - 1);
    }
    __syncthreads();

    if (s_last) {
        __threadfence();
        if (t < BATCH) g_done[t] = 0;                    // reset for next replay
        double v = 0.0;
        if (t < BATCH) v += (double)g_neg[t] * (1.0 / BATCH);
        const float4* gp = (const float4*)g_pos;         // 400 float4
        for (int i = t; i < (BATCH * NBOX) / 4; i += 256) {
            float4 q = gp[i];
            v += ((double)q.x + (double)q.y + (double)q.z + (double)q.w)
                 * (1.0 / (BATCH * NBOX));
        }
        #pragma unroll
        for (int o = 16; o > 0; o >>= 1) v += __shfl_xor_sync(0xffffffffu, v, o);
        if (lane == 0) sdd[t >> 5] = v;
        __syncthreads();
        if (t == 0) {
            double x = 0.0;
            #pragma unroll
            for (int j = 0; j < 8; j++) x += sdd[j];
            out[0] = (float)x;
        }
    }
}

// ---------------- launch ----------------
extern "C" void kernel_launch(void* const* d_in, const int* in_sizes, int n_in,
                              void* d_out, int out_size)
{
    const float* p      = (const float*)d_in[0];
    const float* boxes  = (const float*)d_in[1];
    const int*   labels = (const int*)  d_in[2];
    const float* ancs   = (const float*)d_in[3];
    float*       out    = (float*)d_out;

    dim3 grid(GRID_X, BATCH);
    k_fused<<<grid, 256>>>(p, boxes, labels, ancs, out);
}

// round 16
// speedup vs baseline: 1.3014x; 1.3014x over previous
#include <cuda_runtime.h>
#include <math.h>

#define NANC   10647
#define KSTR   10648                   // padded per-image key stride (even -> 16B-aligned pairs)
#define NBOX   50
#define BATCH  32
#define NCLS   20
#define NUMNEG 1000
#define FIN_TOTAL 64                   // blocks of k_rest gating the final sum

// ---------------- scratch (static device globals: no runtime allocation) ----------------
__device__ __align__(16) unsigned long long g_keys[BATCH * KSTR];
__device__ float               g_neg [BATCH];
__device__ __align__(16) float g_pos [BATCH * NBOX];
__device__ unsigned            g_ctr;                 // final-gate counter (wraps)

// ---------------- constants ----------------
__constant__ float c_asc_x[9] = {10.f/416.f,16.f/416.f,33.f/416.f,30.f/416.f,62.f/416.f,
                                 59.f/416.f,116.f/416.f,156.f/416.f,373.f/416.f};
__constant__ float c_asc_y[9] = {13.f/416.f,30.f/416.f,23.f/416.f,61.f/416.f,45.f/416.f,
                                 119.f/416.f,90.f/416.f,198.f/416.f,326.f/416.f};
__constant__ float c_fs9[9]   = {52.f,52.f,52.f,26.f,26.f,26.f,13.f,13.f,13.f};
__constant__ int   c_cum[3]   = {0, 2704, 3380};
__constant__ int   c_fsl[3]   = {52, 26, 13};

// ---------------- math helpers (identical to the bit-exact R15 run) ----------------
__device__ __forceinline__ float ciou_f(float l1,float t1,float r1,float b1,
                                        float areaE1,float at1,float cx1,float cy1,
                                        float l2,float t2,float r2,float b2,
                                        float area2,float at2,float cx2,float cy2)
{
    float iw = fminf(r1,r2) - fmaxf(l1,l2); iw = fmaxf(iw, 0.f);
    float ih = fminf(b1,b2) - fmaxf(t1,t2); ih = fmaxf(ih, 0.f);
    float inter = iw * ih;
    float uni   = (areaE1 + area2) - inter;
    float iou   = __fdividef(inter, uni);
    float cw = fmaxf(r1,r2) - fminf(l1,l2);
    float ch = fmaxf(b1,b2) - fminf(t1,t2);
    float c2 = fmaf(cw, cw, fmaf(ch, ch, 1e-7f));
    float dx = cx1 - cx2, dy = cy1 - cy2;
    float rho2 = fmaf(dx, dx, dy * dy);
    float dd = at1 - at2;
    float v  = 0.40528473456935109f * dd * dd;
    float den = (1.0000001f - iou) + v;
    float av  = v * __fdividef(v, den);
    return iou - __fdividef(rho2, c2) - av;
}

__device__ __forceinline__ float ciou_f2(float l1,float t1,float r1,float b1,
                                         float areaE1,float at1,float cx1,float cy1,
                                         float l2,float t2,float r2,float b2,
                                         float area2,float at2,float cx2,float cy2)
{
    float iw = fminf(r1,r2) - fmaxf(l1,l2); iw = fmaxf(iw, 0.f);
    float ih = fminf(b1,b2) - fmaxf(t1,t2); ih = fmaxf(ih, 0.f);
    float inter = iw * ih;
    float uni   = (areaE1 + area2) - inter;
    float iou   = __fdividef(inter, uni);
    float cw = fmaxf(r1,r2) - fminf(l1,l2);
    float ch = fmaxf(b1,b2) - fminf(t1,t2);
    float c2 = fmaf(cw, cw, fmaf(ch, ch, 1e-7f));
    float dx = cx1 - cx2, dy = cy1 - cy2;
    float rho2 = fmaf(dx, dx, dy * dy);
    float dd = at1 - at2;
    float v  = 0.40528473456935109f * dd * dd;
    float den = (1.0000001f - iou) + v;
    float num = fmaf(rho2, den, (v * v) * c2);     // rho2*den + v^2*c2
    return iou - __fdividef(num, c2 * den);
}

__device__ __forceinline__ float softplusf(float x){
    return fmaxf(x, 0.f) + log1pf(expf(-fabsf(x)));
}
__device__ __forceinline__ float sigmf(float x){ return 1.f / (1.f + expf(-x)); }
__device__ __forceinline__ float focal0(float x){
    float s = sigmf(x); return softplusf(x) * 0.75f * s * s;
}
__device__ __forceinline__ float focal1(float x){
    float s = sigmf(x); float o = 1.f - s;
    return (softplusf(x) - x) * 0.25f * o * o;
}
__device__ __forceinline__ unsigned ordf(float f){
    unsigned u = __float_as_uint(f);
    return (u & 0x80000000u) ? ~u : (u | 0x80000000u);
}
__device__ __forceinline__ float fs_of(int a){
    return (a < 8112) ? 52.f : ((a < 10140) ? 26.f : 13.f);
}

struct AncReg { float l, t, r, b, area, at, cx, cy; };

__device__ __forceinline__ AncReg decode_anchor(const float* __restrict__ p,
                                                const float* __restrict__ ancs,
                                                int b, int a)
{
    const float* pp = p + ((size_t)b * NANC + a) * 25;
    float4 an = ((const float4*)ancs)[a];
    float fs = fs_of(a);
    float cx = (1.f / (1.f + expf(-pp[0]))) / fs + an.x;
    float cy = (1.f / (1.f + expf(-pp[1]))) / fs + an.y;
    float w  = expf(pp[2]) * an.z;
    float h  = expf(pp[3]) * an.w;
    AncReg R;
    R.l = cx - w * 0.5f; R.t = cy - h * 0.5f;
    R.r = cx + w * 0.5f; R.b = cy + h * 0.5f;
    R.area = w * h;
    R.at   = atanf(w / (h + 1e-7f));
    R.cx   = cx;  R.cy = cy;
    return R;
}

// ---------------- K1: decode + per-anchor max CIoU + OHEM keys (2 anchors/thread) -------------
__global__ void k_decode(const float* __restrict__ p, const float* __restrict__ boxes,
                         const float* __restrict__ ancs)
{
    __shared__ float4 sA[NBOX];   // l,t,r,b
    __shared__ float4 sB[NBOX];   // area+eps, atan, cx, cy
    const int b = blockIdx.y;
    const int t = threadIdx.x;
    if (t < NBOX) {
        float4 bxv = ((const float4*)boxes)[b * NBOX + t];
        sA[t] = bxv;
        float w = bxv.z - bxv.x, h = bxv.w - bxv.y;
        sB[t] = make_float4(w * h + 1e-7f, atanf(w / (h + 1e-7f)),
                            (bxv.x + bxv.z) * 0.5f, (bxv.y + bxv.w) * 0.5f);
    }
    __syncthreads();

    int a0 = (blockIdx.x * 256 + t) * 2;
    if (a0 >= NANC) return;
    const int  a1   = a0 + 1;
    const bool has1 = (a1 < NANC);
    AncReg X = decode_anchor(p, ancs, b, a0);
    AncReg Y = has1 ? decode_anchor(p, ancs, b, a1) : X;

    float mx0 = -1e30f, mx1 = -1e30f;
    #pragma unroll 2
    for (int i = 0; i < NBOX; i++) {
        float4 A  = sA[i];
        float4 Bb = sB[i];
        mx0 = fmaxf(mx0, ciou_f2(A.x, A.y, A.z, A.w, Bb.x, Bb.y, Bb.z, Bb.w,
                                 X.l, X.t, X.r, X.b, X.area, X.at, X.cx, X.cy));
        mx1 = fmaxf(mx1, ciou_f2(A.x, A.y, A.z, A.w, Bb.x, Bb.y, Bb.z, Bb.w,
                                 Y.l, Y.t, Y.r, Y.b, Y.area, Y.at, Y.cx, Y.cy));
    }
    float m0 = (mx0 < 0.5f) ? mx0 : __int_as_float(0x7f800000);
    unsigned long long k0 = (((unsigned long long)ordf(m0)) << 32) | (unsigned)a0;
    if (has1) {
        float m1 = (mx1 < 0.5f) ? mx1 : __int_as_float(0x7f800000);
        unsigned long long k1 = (((unsigned long long)ordf(m1)) << 32) | (unsigned)a1;
        *reinterpret_cast<ulonglong2*>(&g_keys[(size_t)b * KSTR + a0]) =
            make_ulonglong2(k0, k1);   // KSTR even + a0 even -> 16B-aligned STG.128
    } else {
        g_keys[(size_t)b * KSTR + a0] = k0;
    }
}

// ---------------- K2: fused select (1024 thr, smem keys) + positives + final ------------------
__global__ void k_rest(const float* __restrict__ p, const float* __restrict__ boxes,
                       const int* __restrict__ labels, const float* __restrict__ ancs,
                       float* __restrict__ out)
{
    const int b    = blockIdx.y;
    const int bx   = blockIdx.x;       // 0 = select, 1 = positives
    const int t    = threadIdx.x;
    const int lane = t & 31;
    const int wid  = t >> 5;

    if (bx == 0) {
        // ------------------------------- SELECT path -------------------------------
        extern __shared__ unsigned long long sk[];      // NANC keys (85 KB)
        __shared__ unsigned hist[256];
        __shared__ unsigned long long s_pref;
        __shared__ int s_k, s_cnt, s_fin;
        __shared__ float s_red[32];

        if (t == 0) { s_fin = 0; s_cnt = 0; }
        for (int i = t; i < NANC; i += 1024) sk[i] = g_keys[(size_t)b * KSTR + i];
        __syncthreads();

        unsigned long long prefix = 0ull, pmask = 0ull;
        int k = NUMNEG;
        const int shifts[6] = {56, 48, 40, 32, 8, 0};

        for (int pi = 0; pi < 6; pi++) {
            if (pi == 4 && s_fin) break;                // value threshold already exact
            const int shift = shifts[pi];
            if (t < 256) hist[t] = 0u;
            __syncthreads();

            // uniform trip count; interior guarded -> full-mask ballot is legal
            for (int base = 0; base < NANC; base += 1024) {
                int i = base + t;
                bool ok = false; unsigned digit = 0;
                if (i < NANC) {
                    unsigned long long e = sk[i];
                    ok = ((e & pmask) == prefix);
                    digit = (unsigned)(e >> shift) & 255u;
                }
                unsigned bal = __ballot_sync(0xffffffffu, ok);
                if (ok) {
                    unsigned same = __match_any_sync(bal, digit);
                    if (lane == (__ffs(same) - 1))
                        atomicAdd(&hist[digit], __popc(same));
                }
            }
            __syncthreads();

            if (t < 32) {                               // warp-scan over 256 bins
                int lo = t * 8;
                unsigned c[8]; int lsum = 0;
                #pragma unroll
                for (int j = 0; j < 8; j++) { c[j] = hist[lo + j]; lsum += (int)c[j]; }
                int pre = lsum;
                #pragma unroll
                for (int o = 1; o < 32; o <<= 1) {
                    int n = __shfl_up_sync(0xffffffffu, pre, o);
                    if (t >= o) pre += n;
                }
                int excl = pre - lsum;
                if (excl < k && k <= excl + lsum) {
                    int run = excl, d = lo, cc = 0;
                    #pragma unroll
                    for (int j = 0; j < 8; j++) {
                        if (run + (int)c[j] >= k) { d = lo + j; cc = (int)c[j]; break; }
                        run += (int)c[j];
                    }
                    s_pref = prefix | ((unsigned long long)(unsigned)d << shift);
                    s_k    = k - run;
                    s_cnt  = cc;
                }
            }
            __syncthreads();
            prefix = s_pref; k = s_k;
            pmask |= (0xFFull << shift);
            if (pi == 3) {
                pmask |= (0xFFFFull << 16);             // key bytes 3,2 always zero
                if (t == 0) s_fin = (s_k == s_cnt);
            }
            __syncthreads();
        }
        unsigned long long thresh = s_fin ? (prefix | 0xFFFFFFFFull) : prefix;

        float sum = 0.f;                                // exactly NUMNEG keys pass
        for (int i = t; i < NANC; i += 1024) {
            unsigned long long e = sk[i];
            if (e <= thresh) {
                int idx = (int)(unsigned)(e & 0xffffffffu);
                sum += focal0(p[((size_t)b * NANC + idx) * 25 + 4]);
            }
        }
        #pragma unroll
        for (int o = 16; o > 0; o >>= 1) sum += __shfl_xor_sync(0xffffffffu, sum, o);
        if (lane == 0) s_red[wid] = sum;
        __syncthreads();
        if (t == 0) {
            float v = 0.f;
            #pragma unroll
            for (int j = 0; j < 32; j++) v += s_red[j];
            g_neg[b] = v;
        }
    } else {
        // ------------------------------ POSITIVES path ------------------------------
        __shared__ float s_l[NBOX], s_t[NBOX], s_r[NBOX], s_bb[NBOX], s_cx[NBOX], s_cy[NBOX];
        if (t < NBOX) {
            float4 bxv = ((const float4*)boxes)[b * NBOX + t];
            s_l[t] = bxv.x; s_t[t] = bxv.y; s_r[t] = bxv.z; s_bb[t] = bxv.w;
            s_cx[t] = (bxv.x + bxv.z) * 0.5f;
            s_cy[t] = (bxv.y + bxv.w) * 0.5f;
        }
        __syncthreads();

        for (int i = wid; i < NBOX; i += 32) {          // 32 warps, 1-2 boxes each
            float l1 = s_l[i], t1 = s_t[i], r1 = s_r[i], b1 = s_bb[i];
            float w1 = r1 - l1, h1 = b1 - t1;
            float area1  = w1 * h1;
            float areaE1 = area1 + 1e-7f;
            float at1    = atanf(w1 / (h1 + 1e-7f));
            float off1   = (float)i;
            float l1o = l1 + off1, t1o = t1 + off1, r1o = r1 + off1, b1o = b1 + off1;
            float cx1o = (l1o + r1o) * 0.5f, cy1o = (t1o + b1o) * 0.5f;

            float best = -1e30f; int bestj = 1 << 30;
            for (int j = lane; j < NBOX * 9; j += 32) {
                int jb = j / 9, a9 = j - jb * 9;
                float f = c_fs9[a9];
                float acx = floorf(s_cx[jb] * f) / f;
                float acy = floorf(s_cy[jb] * f) / f;
                float aw = c_asc_x[a9], ah = c_asc_y[a9];
                float offj = (float)jb;
                float l2 = acx - aw * 0.5f + offj, t2 = acy - ah * 0.5f + offj;
                float r2 = acx + aw * 0.5f + offj, b2 = acy + ah * 0.5f + offj;
                float w2 = r2 - l2, h2 = b2 - t2;
                float v = ciou_f(l1o, t1o, r1o, b1o, areaE1, at1, cx1o, cy1o,
                                 l2, t2, r2, b2, w2 * h2, atanf(w2 / (h2 + 1e-7f)),
                                 (l2 + r2) * 0.5f, (t2 + b2) * 0.5f);
                if (v > best) { best = v; bestj = j; }
            }
            #pragma unroll
            for (int o = 16; o > 0; o >>= 1) {          // argmax, tie -> smaller j
                float ov = __shfl_xor_sync(0xffffffffu, best, o);
                int   oj = __shfl_xor_sync(0xffffffffu, bestj, o);
                if (ov > best || (ov == best && oj < bestj)) { best = ov; bestj = oj; }
            }
            int kk  = bestj % 9;
            int lev = kk / 3;
            float ff = c_fs9[kk];
            int col = (int)floorf(s_cx[i] * ff);
            int row = (int)floorf(s_cy[i] * ff);
            int midx = (c_cum[lev] + row * c_fsl[lev] + col) * 3 + lev;

            const float* pm = p + ((size_t)b * NANC + midx) * 25;
            int lab = labels[b * NBOX + i] - 1;
            float contrib = 0.f;
            if (lane < NCLS) {
                float x = pm[5 + lane];
                contrib = softplusf(x) - ((lane == lab) ? x : 0.f);
            } else if (lane == NCLS) {
                contrib = focal1(pm[4]);
            } else if (lane == NCLS + 1) {
                float4 an = ((const float4*)ancs)[midx];
                float fsm = fs_of(midx);
                float pcx = (1.f / (1.f + expf(-pm[0]))) / fsm + an.x;
                float pcy = (1.f / (1.f + expf(-pm[1]))) / fsm + an.y;
                float pw  = expf(pm[2]) * an.z;
                float ph  = expf(pm[3]) * an.w;
                float pl = pcx - pw * 0.5f, pt = pcy - ph * 0.5f;
                float pr = pcx + pw * 0.5f, pb = pcy + ph * 0.5f;
                float iou1 = ciou_f(l1, t1, r1, b1, areaE1, at1,
                                    (l1 + r1) * 0.5f, (t1 + b1) * 0.5f,
                                    pl, pt, pr, pb, pw * ph,
                                    atanf(pw / (ph + 1e-7f)), pcx, pcy);
                contrib = (2.f - area1) * (1.f - iou1);
            }
            #pragma unroll
            for (int o = 16; o > 0; o >>= 1)
                contrib += __shfl_xor_sync(0xffffffffu, contrib, o);
            if (lane == 0) g_pos[b * NBOX + i] = contrib;
        }
    }

    // ------------------------------ final gate (64 blocks) ------------------------------
    __shared__ int s_last;
    __shared__ double sdd[32];
    __syncthreads();
    __threadfence();
    if (t == 0) {
        unsigned old = atomicInc(&g_ctr, FIN_TOTAL - 1);
        s_last = (old == FIN_TOTAL - 1);
    }
    __syncthreads();

    if (s_last) {
        __threadfence();
        double v = 0.0;
        if (t < BATCH) v += (double)g_neg[t] * (1.0 / BATCH);
        const float4* gp = (const float4*)g_pos;        // 400 float4
        for (int i = t; i < (BATCH * NBOX) / 4; i += 1024) {
            float4 q = gp[i];
            v += ((double)q.x + (double)q.y + (double)q.z + (double)q.w)
                 * (1.0 / (BATCH * NBOX));
        }
        #pragma unroll
        for (int o = 16; o > 0; o >>= 1) v += __shfl_xor_sync(0xffffffffu, v, o);
        if (lane == 0) sdd[wid] = v;
        __syncthreads();
        if (t == 0) {
            double x = 0.0;
            #pragma unroll
            for (int j = 0; j < 32; j++) x += sdd[j];
            out[0] = (float)x;
        }
    }
}

// ---------------- launch ----------------
extern "C" void kernel_launch(void* const* d_in, const int* in_sizes, int n_in,
                              void* d_out, int out_size)
{
    const float* p      = (const float*)d_in[0];
    const float* boxes  = (const float*)d_in[1];
    const int*   labels = (const int*)  d_in[2];
    const float* ancs   = (const float*)d_in[3];
    float*       out    = (float*)d_out;

    cudaFuncSetAttribute(k_rest, cudaFuncAttributeMaxDynamicSharedMemorySize,
                         (int)(NANC * sizeof(unsigned long long)));

    const int pairs = (NANC + 1) / 2;
    dim3 g1((pairs + 255) / 256, BATCH);
    k_decode<<<g1, 256>>>(p, boxes, ancs);
    dim3 g2(2, BATCH);
    k_rest<<<g2, 1024, NANC * sizeof(unsigned long long)>>>(p, boxes, labels, ancs, out);
}